// round 3
// baseline (speedup 1.0000x reference)
#include <cuda_runtime.h>
#include <cuda_bf16.h>
#include <cstdint>

#define N_NODES 50000
#define MAX_E   800000
#define MAX_TOT (MAX_E + N_NODES)
#define F1 128
#define F2 64

// ---------------- scratch (no allocations allowed) ----------------
__device__ int   g_cnt[N_NODES];
__device__ int   g_cursor[N_NODES];
__device__ int   g_rowptr[N_NODES + 1];
__device__ int   g_col[MAX_TOT];
__device__ float g_nrm[MAX_TOT];
__device__ float g_dinv[N_NODES];
__device__ float g_H1[(size_t)N_NODES * F1];   // x @ W1
__device__ float g_A1[(size_t)N_NODES * F1];   // relu(agg + b1)
__device__ float g_H2[(size_t)N_NODES * F2];   // A1 @ W2
__device__ int   g_is64;

// ---------------- edge dtype probe + init ----------------
__global__ void k_init_detect(const void* ei) {
    int i = blockIdx.x * blockDim.x + threadIdx.x;
    if (i < N_NODES) { g_cnt[i] = 1; g_cursor[i] = 0; }
    if (i == 0) {
        const long long* p = (const long long*)ei;
        int ok = 1;
        for (int j = 0; j < 64; j++) {
            long long v = p[j];
            if (v < 0 || v >= N_NODES) { ok = 0; break; }
        }
        g_is64 = ok;
    }
}

__device__ __forceinline__ int edge_at(const void* ei, int E, int which, int idx) {
    if (g_is64) return (int)((const long long*)ei)[(size_t)which * E + idx];
    return ((const int*)ei)[(size_t)which * E + idx];
}

__global__ void k_degree(const void* __restrict__ ei, int E) {
    int e = blockIdx.x * blockDim.x + threadIdx.x;
    if (e < E) atomicAdd(&g_cnt[edge_at(ei, E, 1, e)], 1);
}

// ---------------- exclusive scan + dinv (single block) ----------------
__global__ void k_scan() {
    const int T = 1024;
    int t = threadIdx.x;
    const int per = (N_NODES + T - 1) / T;
    int s = t * per;
    int e = min(s + per, N_NODES);
    int local = 0;
    for (int i = s; i < e; i++) local += g_cnt[i];
    __shared__ int sm[T];
    sm[t] = local;
    __syncthreads();
    for (int off = 1; off < T; off <<= 1) {
        int v = (t >= off) ? sm[t - off] : 0;
        __syncthreads();
        sm[t] += v;
        __syncthreads();
    }
    int run = sm[t] - local;
    for (int i = s; i < e; i++) {
        int c = g_cnt[i];
        g_rowptr[i] = run;
        run += c;
        g_dinv[i] = rsqrtf((float)c);
    }
    if (t == T - 1) g_rowptr[N_NODES] = sm[T - 1];
}

// ---------------- CSR scatter (edges + self loops) ----------------
__global__ void k_scatter(const void* __restrict__ ei, int E) {
    int i = blockIdx.x * blockDim.x + threadIdx.x;
    int tot = E + N_NODES;
    if (i >= tot) return;
    int s, d;
    if (i < E) { s = edge_at(ei, E, 0, i); d = edge_at(ei, E, 1, i); }
    else       { s = d = i - E; }
    int pos = g_rowptr[d] + atomicAdd(&g_cursor[d], 1);
    g_col[pos] = s;
    g_nrm[pos] = g_dinv[s] * g_dinv[d];
}

// ============ mma.sync bf16 GEMM: C[M,NOUT] = A[M,128] @ W[128,NOUT] ============
// Compensated bf16: A=Ah+Al, W=Wh+Wl; C = Ah*Wh + Ah*Wl + Al*Wh (fp32 accum).
__device__ __forceinline__ void mma_bf16(float* c,
        uint32_t a0, uint32_t a1, uint32_t a2, uint32_t a3,
        uint32_t b0, uint32_t b1) {
    asm volatile("mma.sync.aligned.m16n8k16.row.col.f32.bf16.bf16.f32 "
        "{%0,%1,%2,%3}, {%4,%5,%6,%7}, {%8,%9}, {%0,%1,%2,%3};"
        : "+f"(c[0]), "+f"(c[1]), "+f"(c[2]), "+f"(c[3])
        : "r"(a0), "r"(a1), "r"(a2), "r"(a3), "r"(b0), "r"(b1));
}

template<int NOUT>
__global__ __launch_bounds__(256, 1) void k_gemm_mma(const float* __restrict__ A,
                                                     const float* __restrict__ W,
                                                     float* __restrict__ C, int M) {
    extern __shared__ __align__(16) char smem[];
    const int LDA = 136;   // bf16 elems per row (pad: stride%32banks = 4 -> conflict-free frags)
    __nv_bfloat16* Ah = (__nv_bfloat16*)smem;          // 128 x LDA
    __nv_bfloat16* Al = Ah + 128 * LDA;
    __nv_bfloat16* Bh = Al + 128 * LDA;                // NOUT x LDA (W^T)
    __nv_bfloat16* Bl = Bh + NOUT * LDA;

    int tid = threadIdx.x, lane = tid & 31, wid = tid >> 5;
    int rowBase = blockIdx.x * 128;

    // ---- load + split A tile (fp32 -> bf16 hi/lo) ----
    {
        int r = tid >> 1, c0 = (tid & 1) * 64;
        const float* arow = A + (size_t)(rowBase + r) * 128 + c0;
        bool valid = (rowBase + r) < M;
#pragma unroll
        for (int gi = 0; gi < 16; gi++) {
            float4 v = valid ? *(const float4*)(arow + gi * 4) : make_float4(0.f, 0.f, 0.f, 0.f);
            float f[4] = {v.x, v.y, v.z, v.w};
#pragma unroll
            for (int j = 0; j < 2; j++) {
                __nv_bfloat162 h = __floats2bfloat162_rn(f[2 * j], f[2 * j + 1]);
                float r0 = f[2 * j]     - __bfloat162float(h.x);
                float r1 = f[2 * j + 1] - __bfloat162float(h.y);
                __nv_bfloat162 l = __floats2bfloat162_rn(r0, r1);
                int off = r * LDA + c0 + gi * 4 + 2 * j;
                *(uint32_t*)(Ah + off) = *(uint32_t*)&h;
                *(uint32_t*)(Al + off) = *(uint32_t*)&l;
            }
        }
    }
    // ---- load + transpose + split W: Wt[n][k] ----
    for (int idx = tid * 4; idx < 128 * NOUT; idx += 256 * 4) {
        int k = idx / NOUT, n0 = idx % NOUT;
        float4 w = *(const float4*)(W + idx);
        float wv[4] = {w.x, w.y, w.z, w.w};
#pragma unroll
        for (int j = 0; j < 4; j++) {
            __nv_bfloat16 h = __float2bfloat16_rn(wv[j]);
            __nv_bfloat16 l = __float2bfloat16_rn(wv[j] - __bfloat162float(h));
            Bh[(n0 + j) * LDA + k] = h;
            Bl[(n0 + j) * LDA + k] = l;
        }
    }
    __syncthreads();

    // ---- warp tiling ----
    const int WCOLS = NOUT / 32;          // 4 (128) or 2 (64)
    const int WROWS = 8 / WCOLS;          // 2 or 4
    const int MT    = 128 / (WROWS * 16); // 4 or 2
    int wr = wid / WCOLS, wc = wid % WCOLS;
    int mBase = wr * (MT * 16);
    int nBase = wc * 32;
    int g = lane >> 2, t2 = (lane & 3) * 2;

    float acc[MT][4][4];
#pragma unroll
    for (int mt = 0; mt < MT; mt++)
#pragma unroll
        for (int nt = 0; nt < 4; nt++)
#pragma unroll
            for (int j = 0; j < 4; j++) acc[mt][nt][j] = 0.f;

    for (int ks = 0; ks < 8; ks++) {
        int k0 = ks * 16;
        uint32_t ah[MT][4], al[MT][4];
#pragma unroll
        for (int mt = 0; mt < MT; mt++) {
            int r0 = mBase + mt * 16 + g;
            int o0 = r0 * LDA + k0 + t2;
            int o1 = (r0 + 8) * LDA + k0 + t2;
            ah[mt][0] = *(const uint32_t*)(Ah + o0);
            ah[mt][1] = *(const uint32_t*)(Ah + o1);
            ah[mt][2] = *(const uint32_t*)(Ah + o0 + 8);
            ah[mt][3] = *(const uint32_t*)(Ah + o1 + 8);
            al[mt][0] = *(const uint32_t*)(Al + o0);
            al[mt][1] = *(const uint32_t*)(Al + o1);
            al[mt][2] = *(const uint32_t*)(Al + o0 + 8);
            al[mt][3] = *(const uint32_t*)(Al + o1 + 8);
        }
#pragma unroll
        for (int nt = 0; nt < 4; nt++) {
            int n = nBase + nt * 8 + g;
            int bb = n * LDA + k0 + t2;
            uint32_t bh0 = *(const uint32_t*)(Bh + bb);
            uint32_t bh1 = *(const uint32_t*)(Bh + bb + 8);
            uint32_t bl0 = *(const uint32_t*)(Bl + bb);
            uint32_t bl1 = *(const uint32_t*)(Bl + bb + 8);
#pragma unroll
            for (int mt = 0; mt < MT; mt++) {
                mma_bf16(acc[mt][nt], ah[mt][0], ah[mt][1], ah[mt][2], ah[mt][3], bh0, bh1);
                mma_bf16(acc[mt][nt], ah[mt][0], ah[mt][1], ah[mt][2], ah[mt][3], bl0, bl1);
                mma_bf16(acc[mt][nt], al[mt][0], al[mt][1], al[mt][2], al[mt][3], bh0, bh1);
            }
        }
    }

    // ---- epilogue ----
#pragma unroll
    for (int mt = 0; mt < MT; mt++) {
        int row0 = rowBase + mBase + mt * 16 + g;
#pragma unroll
        for (int nt = 0; nt < 4; nt++) {
            int col = nBase + nt * 8 + t2;
            if (row0 < M)
                *(float2*)(C + (size_t)row0 * NOUT + col) = make_float2(acc[mt][nt][0], acc[mt][nt][1]);
            if (row0 + 8 < M)
                *(float2*)(C + (size_t)(row0 + 8) * NOUT + col) = make_float2(acc[mt][nt][2], acc[mt][nt][3]);
        }
    }
}

// ---------------- layer-1 aggregation + bias + relu ----------------
__global__ __launch_bounds__(256) void k_agg1(const float* __restrict__ b1) {
    int warp = (blockIdx.x * blockDim.x + threadIdx.x) >> 5;
    if (warp >= N_NODES) return;
    int lane = threadIdx.x & 31;
    int beg = g_rowptr[warp], end = g_rowptr[warp + 1];
    float4 acc = make_float4(0.f, 0.f, 0.f, 0.f);
    int j = beg;
    for (; j + 2 <= end; j += 2) {
        int c0 = g_col[j], c1 = g_col[j + 1];
        float w0 = g_nrm[j], w1 = g_nrm[j + 1];
        float4 h0 = *(const float4*)(g_H1 + (size_t)c0 * F1 + (lane << 2));
        float4 h1 = *(const float4*)(g_H1 + (size_t)c1 * F1 + (lane << 2));
        acc.x = fmaf(h0.x, w0, fmaf(h1.x, w1, acc.x));
        acc.y = fmaf(h0.y, w0, fmaf(h1.y, w1, acc.y));
        acc.z = fmaf(h0.z, w0, fmaf(h1.z, w1, acc.z));
        acc.w = fmaf(h0.w, w0, fmaf(h1.w, w1, acc.w));
    }
    if (j < end) {
        int c0 = g_col[j];
        float w0 = g_nrm[j];
        float4 h0 = *(const float4*)(g_H1 + (size_t)c0 * F1 + (lane << 2));
        acc.x = fmaf(h0.x, w0, acc.x);
        acc.y = fmaf(h0.y, w0, acc.y);
        acc.z = fmaf(h0.z, w0, acc.z);
        acc.w = fmaf(h0.w, w0, acc.w);
    }
    float4 bb = *(const float4*)(b1 + (lane << 2));
    float4 o;
    o.x = fmaxf(acc.x + bb.x, 0.f);
    o.y = fmaxf(acc.y + bb.y, 0.f);
    o.z = fmaxf(acc.z + bb.z, 0.f);
    o.w = fmaxf(acc.w + bb.w, 0.f);
    *(float4*)(g_A1 + (size_t)warp * F1 + (lane << 2)) = o;
}

// ---------------- layer-2 aggregation + bias + softmax ----------------
__global__ __launch_bounds__(256) void k_agg2(const float* __restrict__ b2,
                                              float* __restrict__ out) {
    int warp = (blockIdx.x * blockDim.x + threadIdx.x) >> 5;
    if (warp >= N_NODES) return;
    int lane = threadIdx.x & 31;
    int beg = g_rowptr[warp], end = g_rowptr[warp + 1];
    float2 acc = make_float2(0.f, 0.f);
    int j = beg;
    for (; j + 2 <= end; j += 2) {
        int c0 = g_col[j], c1 = g_col[j + 1];
        float w0 = g_nrm[j], w1 = g_nrm[j + 1];
        float2 h0 = *(const float2*)(g_H2 + (size_t)c0 * F2 + (lane << 1));
        float2 h1 = *(const float2*)(g_H2 + (size_t)c1 * F2 + (lane << 1));
        acc.x = fmaf(h0.x, w0, fmaf(h1.x, w1, acc.x));
        acc.y = fmaf(h0.y, w0, fmaf(h1.y, w1, acc.y));
    }
    if (j < end) {
        int c0 = g_col[j];
        float w0 = g_nrm[j];
        float2 h0 = *(const float2*)(g_H2 + (size_t)c0 * F2 + (lane << 1));
        acc.x = fmaf(h0.x, w0, acc.x);
        acc.y = fmaf(h0.y, w0, acc.y);
    }
    float2 bb = *(const float2*)(b2 + (lane << 1));
    float l0 = acc.x + bb.x;
    float l1 = acc.y + bb.y;
    float m = fmaxf(l0, l1);
#pragma unroll
    for (int o = 16; o > 0; o >>= 1)
        m = fmaxf(m, __shfl_xor_sync(0xffffffffu, m, o));
    float e0 = __expf(l0 - m);
    float e1 = __expf(l1 - m);
    float s = e0 + e1;
#pragma unroll
    for (int o = 16; o > 0; o >>= 1)
        s += __shfl_xor_sync(0xffffffffu, s, o);
    float inv = 1.0f / s;
    *(float2*)(out + (size_t)warp * F2 + (lane << 1)) = make_float2(e0 * inv, e1 * inv);
}

// ---------------- launch ----------------
extern "C" void kernel_launch(void* const* d_in, const int* in_sizes, int n_in,
                              void* d_out, int out_size) {
    const float* x  = (const float*)d_in[0];
    const void*  ei = d_in[1];
    const float* W1 = (const float*)d_in[2];
    const float* b1 = (const float*)d_in[3];
    const float* W2 = (const float*)d_in[4];
    const float* b2 = (const float*)d_in[5];
    float* out = (float*)d_out;
    int E = in_sizes[1] / 2;

    float *H1, *A1, *H2;
    cudaGetSymbolAddress((void**)&H1, g_H1);
    cudaGetSymbolAddress((void**)&A1, g_A1);
    cudaGetSymbolAddress((void**)&H2, g_H2);

    const int nTiles = (N_NODES + 127) / 128;                     // 391
    const int LDA = 136;
    const int SMEM1 = (128 + 128 + 128 + 128) * LDA * 2;          // 139264
    const int SMEM2 = (128 + 128 + 64 + 64) * LDA * 2;            // 104448
    cudaFuncSetAttribute(k_gemm_mma<128>, cudaFuncAttributeMaxDynamicSharedMemorySize, SMEM1);
    cudaFuncSetAttribute(k_gemm_mma<64>,  cudaFuncAttributeMaxDynamicSharedMemorySize, SMEM2);

    k_init_detect<<<(N_NODES + 255) / 256, 256>>>(ei);
    k_degree<<<(E + 255) / 256, 256>>>(ei, E);
    k_scan<<<1, 1024>>>();
    k_scatter<<<(E + N_NODES + 255) / 256, 256>>>(ei, E);

    k_gemm_mma<128><<<nTiles, 256, SMEM1>>>(x, W1, H1, N_NODES);
    k_agg1<<<(N_NODES * 32 + 255) / 256, 256>>>(b1);
    k_gemm_mma<64><<<nTiles, 256, SMEM2>>>(A1, W2, H2, N_NODES);
    k_agg2<<<(N_NODES * 32 + 255) / 256, 256>>>(b2, out);
}